// round 1
// baseline (speedup 1.0000x reference)
#include <cuda_runtime.h>
#include <math.h>

#define LCc 1024
#define LQq 512
#define NB  64
#define ND  256

// ---------------- scratch (static device allocations are allowed) ----------
__device__ float g_S[(size_t)NB * LCc * LQq];   // 128 MB: S, then overwritten with E = exp(S - rowmax)
__device__ float g_M[(size_t)NB * LQq * ND];    // 32 MB:  M = S2^T @ C
__device__ float g_sub0[NB * LCc];
__device__ float g_sub1[NB * LQq];
__device__ float g_rfac[NB * LCc];              // exp(rowmax)
__device__ float g_invrs[NB * LCc];             // 1 / rowsum
__device__ float g_csum2[NB * LQq];             // sum_c E * rfac[c]

// ---------------- k_init: zero csum2 (atomic accumulation target) ----------
__global__ void k_init() {
    int i = blockIdx.x * blockDim.x + threadIdx.x;
    if (i < NB * LQq) g_csum2[i] = 0.f;
}

// ---------------- k0: sub0 = C@w4C, sub1 = Q@w4Q (warp per row) ------------
__global__ __launch_bounds__(256) void k0_sub(const float* __restrict__ C,
                                              const float* __restrict__ Q,
                                              const float* __restrict__ w4C,
                                              const float* __restrict__ w4Q) {
    int gw   = (blockIdx.x * blockDim.x + threadIdx.x) >> 5;
    int lane = threadIdx.x & 31;
    const float* src; const float* w; float* dst;
    if (gw < NB * LCc) {                 // C rows: gw = c*NB + b
        src = C + (size_t)gw * ND;
        w   = w4C;
        int c = gw / NB, b = gw % NB;
        dst = g_sub0 + b * LCc + c;
    } else {
        int r = gw - NB * LCc;
        if (r >= NB * LQq) return;
        src = Q + (size_t)r * ND;
        w   = w4Q;
        int q = r / NB, b = r % NB;
        dst = g_sub1 + b * LQq + q;
    }
    float acc = 0.f;
    const float4* s4 = (const float4*)src;
    const float4* w4 = (const float4*)w;
#pragma unroll
    for (int j = 0; j < 2; ++j) {
        float4 a  = s4[lane + 32 * j];
        float4 ww = w4[lane + 32 * j];
        acc += a.x * ww.x + a.y * ww.y + a.z * ww.z + a.w * ww.w;
    }
#pragma unroll
    for (int off = 16; off; off >>= 1) acc += __shfl_xor_sync(0xffffffffu, acc, off);
    if (lane == 0) *dst = acc;
}

// ---------------- k1: S = C @ (wml*Q)^T + sub0 + sub1 + bias ---------------
// grid (LQq/64, LCc/64, NB), block 256, 64x64 tile, 4x4 microtile, k-chunk 16
__global__ __launch_bounds__(256) void k1_scores(const float* __restrict__ C,
                                                 const float* __restrict__ Q,
                                                 const float* __restrict__ w4mlu,
                                                 const float* __restrict__ bias) {
    __shared__ float As[16][68];
    __shared__ float Bs[16][68];
    __shared__ float wml[ND];
    const int b  = blockIdx.z;
    const int c0 = blockIdx.y * 64;
    const int q0 = blockIdx.x * 64;
    const int tid = threadIdx.x;
    wml[tid] = w4mlu[tid];
    const int tx = tid & 15, ty = tid >> 4;
    const int rowA = tid >> 2;          // 0..63
    const int kseg = (tid & 3) * 4;     // 0,4,8,12
    const float* Cb = C + (size_t)b * ND;   // (c,d) at Cb + c*NB*ND + d
    const float* Qb = Q + (size_t)b * ND;
    float acc[4][4] = {};
    __syncthreads();
    for (int k0 = 0; k0 < ND; k0 += 16) {
        float4 av = *(const float4*)(Cb + (size_t)(c0 + rowA) * (NB * ND) + k0 + kseg);
        float4 bv = *(const float4*)(Qb + (size_t)(q0 + rowA) * (NB * ND) + k0 + kseg);
        bv.x *= wml[k0 + kseg + 0]; bv.y *= wml[k0 + kseg + 1];
        bv.z *= wml[k0 + kseg + 2]; bv.w *= wml[k0 + kseg + 3];
        As[kseg + 0][rowA] = av.x; As[kseg + 1][rowA] = av.y;
        As[kseg + 2][rowA] = av.z; As[kseg + 3][rowA] = av.w;
        Bs[kseg + 0][rowA] = bv.x; Bs[kseg + 1][rowA] = bv.y;
        Bs[kseg + 2][rowA] = bv.z; Bs[kseg + 3][rowA] = bv.w;
        __syncthreads();
#pragma unroll
        for (int kk = 0; kk < 16; ++kk) {
            float4 a4 = *(const float4*)&As[kk][ty * 4];
            float4 b4 = *(const float4*)&Bs[kk][tx * 4];
            float a_[4] = {a4.x, a4.y, a4.z, a4.w};
            float b_[4] = {b4.x, b4.y, b4.z, b4.w};
#pragma unroll
            for (int i = 0; i < 4; ++i)
#pragma unroll
                for (int j = 0; j < 4; ++j) acc[i][j] += a_[i] * b_[j];
        }
        __syncthreads();
    }
    const float bsv = bias[0];
    float s0v[4], s1v[4];
#pragma unroll
    for (int i = 0; i < 4; ++i) s0v[i] = g_sub0[b * LCc + c0 + ty * 4 + i] + bsv;
#pragma unroll
    for (int j = 0; j < 4; ++j) s1v[j] = g_sub1[b * LQq + q0 + tx * 4 + j];
    float* Sp = g_S + ((size_t)b * LCc + c0) * LQq + q0;
#pragma unroll
    for (int i = 0; i < 4; ++i) {
        float4 o;
        o.x = acc[i][0] + s0v[i] + s1v[0];
        o.y = acc[i][1] + s0v[i] + s1v[1];
        o.z = acc[i][2] + s0v[i] + s1v[2];
        o.w = acc[i][3] + s0v[i] + s1v[3];
        *(float4*)(Sp + (size_t)(ty * 4 + i) * LQq + tx * 4) = o;
    }
}

// ---------------- k2: row stats + overwrite S with E = exp(S - rowmax) -----
// warp per (b,c) row; 512 floats live entirely in registers
__global__ __launch_bounds__(256) void k2_row() {
    int r    = blockIdx.x * 8 + (threadIdx.x >> 5);   // r = b*LCc + c
    int lane = threadIdx.x & 31;
    float4* row = (float4*)(g_S + (size_t)r * LQq);
    float4 v[4];
#pragma unroll
    for (int j = 0; j < 4; ++j) v[j] = row[lane + 32 * j];
    float m = -1e30f;
#pragma unroll
    for (int j = 0; j < 4; ++j)
        m = fmaxf(m, fmaxf(fmaxf(v[j].x, v[j].y), fmaxf(v[j].z, v[j].w)));
#pragma unroll
    for (int off = 16; off; off >>= 1) m = fmaxf(m, __shfl_xor_sync(0xffffffffu, m, off));
    float s = 0.f;
#pragma unroll
    for (int j = 0; j < 4; ++j) {
        v[j].x = expf(v[j].x - m); v[j].y = expf(v[j].y - m);
        v[j].z = expf(v[j].z - m); v[j].w = expf(v[j].w - m);
        s += v[j].x + v[j].y + v[j].z + v[j].w;
    }
#pragma unroll
    for (int off = 16; off; off >>= 1) s += __shfl_xor_sync(0xffffffffu, s, off);
#pragma unroll
    for (int j = 0; j < 4; ++j) row[lane + 32 * j] = v[j];
    if (lane == 0) { g_rfac[r] = expf(m); g_invrs[r] = 1.0f / s; }
}

// ---------------- k3: csum2[b,q] += sum over a 128-c chunk of E*rfac -------
// grid (LQq/128, LCc/128, NB), block 128, coalesced over q
__global__ __launch_bounds__(128) void k3_col() {
    const int q  = blockIdx.x * 128 + threadIdx.x;
    const int b  = blockIdx.z;
    const int cb = blockIdx.y * 128;
    const float* Ep = g_S + ((size_t)b * LCc + cb) * LQq + q;
    const float* rf = g_rfac + b * LCc + cb;
    float acc = 0.f;
#pragma unroll 4
    for (int cc = 0; cc < 128; ++cc) acc += Ep[(size_t)cc * LQq] * rf[cc];
    atomicAdd(&g_csum2[b * LQq + q], acc);
}

// ---------------- k4: M = S2^T @ C  (A-tile = E*rfac, epilogue /csum2) -----
// grid (ND/64, LQq/64, NB), block 256
__global__ __launch_bounds__(256) void k4_M(const float* __restrict__ C) {
    __shared__ float As[16][68];   // As[cc][q]
    __shared__ float Bs[16][68];   // Bs[cc][d]
    const int b = blockIdx.z, q0 = blockIdx.y * 64, d0 = blockIdx.x * 64;
    const int tid = threadIdx.x, tx = tid & 15, ty = tid >> 4;
    const int rrow = tid >> 4;          // 0..15
    const int rseg = (tid & 15) * 4;    // 0..60
    const float* Eb = g_S + (size_t)b * LCc * LQq;
    const float* Cb = C + (size_t)b * ND;
    const float* rf = g_rfac + b * LCc;
    float acc[4][4] = {};
    for (int cb = 0; cb < LCc; cb += 16) {
        float r = rf[cb + rrow];
        float4 ev = *(const float4*)(Eb + (size_t)(cb + rrow) * LQq + q0 + rseg);
        ev.x *= r; ev.y *= r; ev.z *= r; ev.w *= r;
        *(float4*)&As[rrow][rseg] = ev;
        float4 cv = *(const float4*)(Cb + (size_t)(cb + rrow) * (NB * ND) + d0 + rseg);
        *(float4*)&Bs[rrow][rseg] = cv;
        __syncthreads();
#pragma unroll
        for (int kk = 0; kk < 16; ++kk) {
            float4 a4 = *(const float4*)&As[kk][ty * 4];
            float4 b4 = *(const float4*)&Bs[kk][tx * 4];
            float a_[4] = {a4.x, a4.y, a4.z, a4.w};
            float b_[4] = {b4.x, b4.y, b4.z, b4.w};
#pragma unroll
            for (int i = 0; i < 4; ++i)
#pragma unroll
                for (int j = 0; j < 4; ++j) acc[i][j] += a_[i] * b_[j];
        }
        __syncthreads();
    }
    float* Mp = g_M + ((size_t)b * LQq + q0) * ND + d0;
#pragma unroll
    for (int i = 0; i < 4; ++i) {
        float inv = 1.0f / g_csum2[b * LQq + q0 + ty * 4 + i];
        float4 o = {acc[i][0] * inv, acc[i][1] * inv, acc[i][2] * inv, acc[i][3] * inv};
        *(float4*)(Mp + (size_t)(ty * 4 + i) * ND + tx * 4) = o;
    }
}

// ---------------- k5: A = S1@Q, B_ = S1@M, fused transposed-concat out -----
// grid (ND/64, LCc/64, NB), block 256
__global__ __launch_bounds__(256) void k5_out(const float* __restrict__ C,
                                              const float* __restrict__ Q,
                                              float* __restrict__ out) {
    __shared__ float As[16][68];   // As[qq][c]  (S1 numerator E)
    __shared__ float Bq[16][68];   // Bq[qq][d]  (Q)
    __shared__ float Bm[16][68];   // Bm[qq][d]  (M)
    __shared__ float Cs[64][65];   // Cs[d][c]   (C tile, transposed)
    __shared__ float Tr[64][65];   // Tr[c][d]   (transpose staging)
    const int b = blockIdx.z, c0 = blockIdx.y * 64, d0 = blockIdx.x * 64;
    const int tid = threadIdx.x, tx = tid & 15, ty = tid >> 4;
    const int rowA = tid >> 2, ksegA = (tid & 3) * 4;
    const int rrow = tid >> 4, rseg = (tid & 15) * 4;
    const float* Eb = g_S + (size_t)b * LCc * LQq;
    const float* Qb = Q + (size_t)b * ND;
    const float* Mb = g_M + (size_t)b * LQq * ND;
    float accA[4][4] = {}, accB[4][4] = {};
    for (int k0 = 0; k0 < LQq; k0 += 16) {
        float4 ev = *(const float4*)(Eb + (size_t)(c0 + rowA) * LQq + k0 + ksegA);
        As[ksegA + 0][rowA] = ev.x; As[ksegA + 1][rowA] = ev.y;
        As[ksegA + 2][rowA] = ev.z; As[ksegA + 3][rowA] = ev.w;
        float4 qv = *(const float4*)(Qb + (size_t)(k0 + rrow) * (NB * ND) + d0 + rseg);
        *(float4*)&Bq[rrow][rseg] = qv;
        float4 mv = *(const float4*)(Mb + (size_t)(k0 + rrow) * ND + d0 + rseg);
        *(float4*)&Bm[rrow][rseg] = mv;
        __syncthreads();
#pragma unroll
        for (int kk = 0; kk < 16; ++kk) {
            float4 a4 = *(const float4*)&As[kk][ty * 4];
            float4 q4 = *(const float4*)&Bq[kk][tx * 4];
            float4 m4 = *(const float4*)&Bm[kk][tx * 4];
            float a_[4] = {a4.x, a4.y, a4.z, a4.w};
            float qb_[4] = {q4.x, q4.y, q4.z, q4.w};
            float mb_[4] = {m4.x, m4.y, m4.z, m4.w};
#pragma unroll
            for (int i = 0; i < 4; ++i)
#pragma unroll
                for (int j = 0; j < 4; ++j) {
                    accA[i][j] += a_[i] * qb_[j];
                    accB[i][j] += a_[i] * mb_[j];
                }
        }
        __syncthreads();
    }
    // apply softmax row normalization (1/rowsum)
#pragma unroll
    for (int i = 0; i < 4; ++i) {
        float inv = g_invrs[b * LCc + c0 + ty * 4 + i];
#pragma unroll
        for (int j = 0; j < 4; ++j) { accA[i][j] *= inv; accB[i][j] *= inv; }
    }
    // load C tile transposed: Cs[d][c] = C[c,b,d]
    {
        int cl = tid >> 2;
        int ds = (tid & 3) * 4;
#pragma unroll
        for (int dd = 0; dd < 64; dd += 16) {
            float4 cv = *(const float4*)(C + ((size_t)(c0 + cl) * NB + b) * ND + d0 + dd + ds);
            Cs[dd + ds + 0][cl] = cv.x; Cs[dd + ds + 1][cl] = cv.y;
            Cs[dd + ds + 2][cl] = cv.z; Cs[dd + ds + 3][cl] = cv.w;
        }
    }
    // stage A for transpose
#pragma unroll
    for (int i = 0; i < 4; ++i)
#pragma unroll
        for (int j = 0; j < 4; ++j) Tr[ty * 4 + i][tx * 4 + j] = accA[i][j];
    __syncthreads();
    const int cr = tid & 63;
    const int db = tid >> 6;
    const size_t ob = (size_t)b * (4 * ND) * LCc;
#pragma unroll
    for (int rr = 0; rr < 16; ++rr) {
        int dr = db + rr * 4;
        float cval = Cs[dr][cr];
        float aval = Tr[cr][dr];
        size_t col = (size_t)(c0 + cr);
        out[ob + (size_t)(d0 + dr) * LCc + col]            = cval;         // C
        out[ob + (size_t)(ND + d0 + dr) * LCc + col]       = aval;         // A
        out[ob + (size_t)(2 * ND + d0 + dr) * LCc + col]   = cval * aval;  // C*A
    }
    __syncthreads();
#pragma unroll
    for (int i = 0; i < 4; ++i)
#pragma unroll
        for (int j = 0; j < 4; ++j) Tr[ty * 4 + i][tx * 4 + j] = accB[i][j];
    __syncthreads();
#pragma unroll
    for (int rr = 0; rr < 16; ++rr) {
        int dr = db + rr * 4;
        out[ob + (size_t)(3 * ND + d0 + dr) * LCc + (size_t)(c0 + cr)] = Cs[dr][cr] * Tr[cr][dr];  // C*B_
    }
}

// ---------------------------------------------------------------------------
extern "C" void kernel_launch(void* const* d_in, const int* in_sizes, int n_in,
                              void* d_out, int out_size) {
    const float* C     = (const float*)d_in[0];
    const float* Q     = (const float*)d_in[1];
    const float* w4C   = (const float*)d_in[2];
    const float* w4Q   = (const float*)d_in[3];
    const float* w4mlu = (const float*)d_in[4];
    const float* bias  = (const float*)d_in[5];
    float* out = (float*)d_out;

    k_init<<<(NB * LQq + 255) / 256, 256>>>();
    k0_sub<<<(NB * LCc + NB * LQq) / 8, 256>>>(C, Q, w4C, w4Q);
    k1_scores<<<dim3(LQq / 64, LCc / 64, NB), 256>>>(C, Q, w4mlu, bias);
    k2_row<<<NB * LCc / 8, 256>>>();
    k3_col<<<dim3(LQq / 128, LCc / 128, NB), 128>>>();
    k4_M<<<dim3(ND / 64, LQq / 64, NB), 256>>>(C);
    k5_out<<<dim3(ND / 64, LCc / 64, NB), 256>>>(C, Q, out);
}

// round 2
// speedup vs baseline: 1.0260x; 1.0260x over previous
#include <cuda_runtime.h>
#include <math.h>

#define LCc 1024
#define LQq 512
#define NB  64
#define ND  256

// ---------------- scratch ---------------------------------------------------
__device__ float g_S[(size_t)NB * LCc * LQq];   // S, then E = exp(S - rowmax)
__device__ float g_M[(size_t)NB * LQq * ND];    // M = S2^T @ C
__device__ float g_sub0[NB * LCc];
__device__ float g_sub1[NB * LQq];
__device__ float g_rfac[NB * LCc];              // exp(rowmax)
__device__ float g_invrs[NB * LCc];             // 1 / rowsum
__device__ float g_csum2[NB * LQq];             // sum_c E * rfac[c]

// ---------------- packed f32x2 helpers --------------------------------------
typedef unsigned long long u64t;
__device__ __forceinline__ u64t pack_dup(float a) {
    u64t r; asm("mov.b64 %0, {%1,%1};" : "=l"(r) : "f"(a)); return r;
}
__device__ __forceinline__ void fma2(u64t& d, u64t a, u64t b) {
    asm("fma.rn.f32x2 %0, %1, %2, %0;" : "+l"(d) : "l"(a), "l"(b));
}
__device__ __forceinline__ float2 unpack2(u64t v) {
    float2 f; asm("mov.b64 {%0,%1}, %2;" : "=f"(f.x), "=f"(f.y) : "l"(v)); return f;
}

// ---------------- k_init ----------------------------------------------------
__global__ void k_init() {
    int i = blockIdx.x * blockDim.x + threadIdx.x;
    if (i < NB * LQq) g_csum2[i] = 0.f;
}

// ---------------- k0: sub0 = C@w4C, sub1 = Q@w4Q ----------------------------
__global__ __launch_bounds__(256) void k0_sub(const float* __restrict__ C,
                                              const float* __restrict__ Q,
                                              const float* __restrict__ w4C,
                                              const float* __restrict__ w4Q) {
    int gw   = (blockIdx.x * blockDim.x + threadIdx.x) >> 5;
    int lane = threadIdx.x & 31;
    const float* src; const float* w; float* dst;
    if (gw < NB * LCc) {
        src = C + (size_t)gw * ND;
        w   = w4C;
        int c = gw / NB, b = gw % NB;
        dst = g_sub0 + b * LCc + c;
    } else {
        int r = gw - NB * LCc;
        if (r >= NB * LQq) return;
        src = Q + (size_t)r * ND;
        w   = w4Q;
        int q = r / NB, b = r % NB;
        dst = g_sub1 + b * LQq + q;
    }
    float acc = 0.f;
    const float4* s4 = (const float4*)src;
    const float4* w4 = (const float4*)w;
#pragma unroll
    for (int j = 0; j < 2; ++j) {
        float4 a  = s4[lane + 32 * j];
        float4 ww = w4[lane + 32 * j];
        acc += a.x * ww.x + a.y * ww.y + a.z * ww.z + a.w * ww.w;
    }
#pragma unroll
    for (int off = 16; off; off >>= 1) acc += __shfl_xor_sync(0xffffffffu, acc, off);
    if (lane == 0) *dst = acc;
}

// ---------------- k1: S = C @ (wml*Q)^T + sub0 + sub1 + bias ----------------
__global__ __launch_bounds__(256) void k1_scores(const float* __restrict__ C,
                                                 const float* __restrict__ Q,
                                                 const float* __restrict__ w4mlu,
                                                 const float* __restrict__ bias) {
    __shared__ float As[16][68];
    __shared__ float Bs[16][68];
    __shared__ float wml[ND];
    const int b  = blockIdx.z;
    const int c0 = blockIdx.y * 64;
    const int q0 = blockIdx.x * 64;
    const int tid = threadIdx.x;
    wml[tid] = w4mlu[tid];
    const int tx = tid & 15, ty = tid >> 4;
    const int rowA = tid >> 2;
    const int kseg = (tid & 3) * 4;
    const float* Cb = C + (size_t)b * ND;
    const float* Qb = Q + (size_t)b * ND;
    u64t acc2[4][2] = {};
    __syncthreads();
    for (int k0 = 0; k0 < ND; k0 += 16) {
        float4 av = *(const float4*)(Cb + (size_t)(c0 + rowA) * (NB * ND) + k0 + kseg);
        float4 bv = *(const float4*)(Qb + (size_t)(q0 + rowA) * (NB * ND) + k0 + kseg);
        bv.x *= wml[k0 + kseg + 0]; bv.y *= wml[k0 + kseg + 1];
        bv.z *= wml[k0 + kseg + 2]; bv.w *= wml[k0 + kseg + 3];
        As[kseg + 0][rowA] = av.x; As[kseg + 1][rowA] = av.y;
        As[kseg + 2][rowA] = av.z; As[kseg + 3][rowA] = av.w;
        Bs[kseg + 0][rowA] = bv.x; Bs[kseg + 1][rowA] = bv.y;
        Bs[kseg + 2][rowA] = bv.z; Bs[kseg + 3][rowA] = bv.w;
        __syncthreads();
#pragma unroll
        for (int kk = 0; kk < 16; ++kk) {
            float4 a4 = *(const float4*)&As[kk][ty * 4];
            ulonglong2 bp = *(const ulonglong2*)&Bs[kk][tx * 4];
            float a_[4] = {a4.x, a4.y, a4.z, a4.w};
#pragma unroll
            for (int i = 0; i < 4; ++i) {
                u64t ad = pack_dup(a_[i]);
                fma2(acc2[i][0], ad, bp.x);
                fma2(acc2[i][1], ad, bp.y);
            }
        }
        __syncthreads();
    }
    const float bsv = bias[0];
    float s0v[4], s1v[4];
#pragma unroll
    for (int i = 0; i < 4; ++i) s0v[i] = g_sub0[b * LCc + c0 + ty * 4 + i] + bsv;
#pragma unroll
    for (int j = 0; j < 4; ++j) s1v[j] = g_sub1[b * LQq + q0 + tx * 4 + j];
    float* Sp = g_S + ((size_t)b * LCc + c0) * LQq + q0;
#pragma unroll
    for (int i = 0; i < 4; ++i) {
        float2 p0 = unpack2(acc2[i][0]);
        float2 p1 = unpack2(acc2[i][1]);
        float4 o;
        o.x = p0.x + s0v[i] + s1v[0];
        o.y = p0.y + s0v[i] + s1v[1];
        o.z = p1.x + s0v[i] + s1v[2];
        o.w = p1.y + s0v[i] + s1v[3];
        *(float4*)(Sp + (size_t)(ty * 4 + i) * LQq + tx * 4) = o;
    }
}

// ---------------- k2: row stats + overwrite S with E ------------------------
__global__ __launch_bounds__(256) void k2_row() {
    int r    = blockIdx.x * 8 + (threadIdx.x >> 5);
    int lane = threadIdx.x & 31;
    float4* row = (float4*)(g_S + (size_t)r * LQq);
    float4 v[4];
#pragma unroll
    for (int j = 0; j < 4; ++j) v[j] = row[lane + 32 * j];
    float m = -1e30f;
#pragma unroll
    for (int j = 0; j < 4; ++j)
        m = fmaxf(m, fmaxf(fmaxf(v[j].x, v[j].y), fmaxf(v[j].z, v[j].w)));
#pragma unroll
    for (int off = 16; off; off >>= 1) m = fmaxf(m, __shfl_xor_sync(0xffffffffu, m, off));
    float s = 0.f;
#pragma unroll
    for (int j = 0; j < 4; ++j) {
        v[j].x = expf(v[j].x - m); v[j].y = expf(v[j].y - m);
        v[j].z = expf(v[j].z - m); v[j].w = expf(v[j].w - m);
        s += v[j].x + v[j].y + v[j].z + v[j].w;
    }
#pragma unroll
    for (int off = 16; off; off >>= 1) s += __shfl_xor_sync(0xffffffffu, s, off);
#pragma unroll
    for (int j = 0; j < 4; ++j) row[lane + 32 * j] = v[j];
    if (lane == 0) { g_rfac[r] = expf(m); g_invrs[r] = 1.0f / s; }
}

// ---------------- k3: csum2 partial column sums ------------------------------
__global__ __launch_bounds__(128) void k3_col() {
    const int q  = blockIdx.x * 128 + threadIdx.x;
    const int b  = blockIdx.z;
    const int cb = blockIdx.y * 128;
    const float* Ep = g_S + ((size_t)b * LCc + cb) * LQq + q;
    const float* rf = g_rfac + b * LCc + cb;
    float acc = 0.f;
#pragma unroll 4
    for (int cc = 0; cc < 128; ++cc) acc += Ep[(size_t)cc * LQq] * rf[cc];
    atomicAdd(&g_csum2[b * LQq + q], acc);
}

// ---------------- k4: M = S2^T @ C ------------------------------------------
__global__ __launch_bounds__(256) void k4_M(const float* __restrict__ C) {
    __shared__ float As[16][68];
    __shared__ float Bs[16][68];
    const int b = blockIdx.z, q0 = blockIdx.y * 64, d0 = blockIdx.x * 64;
    const int tid = threadIdx.x, tx = tid & 15, ty = tid >> 4;
    const int rrow = tid >> 4;
    const int rseg = (tid & 15) * 4;
    const float* Eb = g_S + (size_t)b * LCc * LQq;
    const float* Cb = C + (size_t)b * ND;
    const float* rf = g_rfac + b * LCc;
    u64t acc2[4][2] = {};
    for (int cb = 0; cb < LCc; cb += 16) {
        float r = rf[cb + rrow];
        float4 ev = *(const float4*)(Eb + (size_t)(cb + rrow) * LQq + q0 + rseg);
        ev.x *= r; ev.y *= r; ev.z *= r; ev.w *= r;
        *(float4*)&As[rrow][rseg] = ev;
        float4 cv = *(const float4*)(Cb + (size_t)(cb + rrow) * (NB * ND) + d0 + rseg);
        *(float4*)&Bs[rrow][rseg] = cv;
        __syncthreads();
#pragma unroll
        for (int kk = 0; kk < 16; ++kk) {
            float4 a4 = *(const float4*)&As[kk][ty * 4];
            ulonglong2 bp = *(const ulonglong2*)&Bs[kk][tx * 4];
            float a_[4] = {a4.x, a4.y, a4.z, a4.w};
#pragma unroll
            for (int i = 0; i < 4; ++i) {
                u64t ad = pack_dup(a_[i]);
                fma2(acc2[i][0], ad, bp.x);
                fma2(acc2[i][1], ad, bp.y);
            }
        }
        __syncthreads();
    }
    float* Mp = g_M + ((size_t)b * LQq + q0) * ND + d0;
#pragma unroll
    for (int i = 0; i < 4; ++i) {
        float inv = 1.0f / g_csum2[b * LQq + q0 + ty * 4 + i];
        float2 p0 = unpack2(acc2[i][0]);
        float2 p1 = unpack2(acc2[i][1]);
        float4 o = {p0.x * inv, p0.y * inv, p1.x * inv, p1.y * inv};
        *(float4*)(Mp + (size_t)(ty * 4 + i) * ND + tx * 4) = o;
    }
}

// ---------------- k5: A = S1@Q, B_ = S1@M, fused transposed-concat ----------
__global__ __launch_bounds__(256) void k5_out(const float* __restrict__ C,
                                              const float* __restrict__ Q,
                                              float* __restrict__ out) {
    __shared__ float As[16][68];
    __shared__ float Bq[16][68];
    __shared__ float Bm[16][68];
    __shared__ float Cs[64][65];
    __shared__ float Tr[64][65];
    const int b = blockIdx.z, c0 = blockIdx.y * 64, d0 = blockIdx.x * 64;
    const int tid = threadIdx.x, tx = tid & 15, ty = tid >> 4;
    const int rowA = tid >> 2, ksegA = (tid & 3) * 4;
    const int rrow = tid >> 4, rseg = (tid & 15) * 4;
    const float* Eb = g_S + (size_t)b * LCc * LQq;
    const float* Qb = Q + (size_t)b * ND;
    const float* Mb = g_M + (size_t)b * LQq * ND;
    u64t accA2[4][2] = {}, accB2[4][2] = {};
    for (int k0 = 0; k0 < LQq; k0 += 16) {
        float4 ev = *(const float4*)(Eb + (size_t)(c0 + rowA) * LQq + k0 + ksegA);
        As[ksegA + 0][rowA] = ev.x; As[ksegA + 1][rowA] = ev.y;
        As[ksegA + 2][rowA] = ev.z; As[ksegA + 3][rowA] = ev.w;
        float4 qv = *(const float4*)(Qb + (size_t)(k0 + rrow) * (NB * ND) + d0 + rseg);
        *(float4*)&Bq[rrow][rseg] = qv;
        float4 mv = *(const float4*)(Mb + (size_t)(k0 + rrow) * ND + d0 + rseg);
        *(float4*)&Bm[rrow][rseg] = mv;
        __syncthreads();
#pragma unroll
        for (int kk = 0; kk < 16; ++kk) {
            float4 a4 = *(const float4*)&As[kk][ty * 4];
            ulonglong2 qp = *(const ulonglong2*)&Bq[kk][tx * 4];
            ulonglong2 mp = *(const ulonglong2*)&Bm[kk][tx * 4];
            float a_[4] = {a4.x, a4.y, a4.z, a4.w};
#pragma unroll
            for (int i = 0; i < 4; ++i) {
                u64t ad = pack_dup(a_[i]);
                fma2(accA2[i][0], ad, qp.x);
                fma2(accA2[i][1], ad, qp.y);
                fma2(accB2[i][0], ad, mp.x);
                fma2(accB2[i][1], ad, mp.y);
            }
        }
        __syncthreads();
    }
    float accA[4][4], accB[4][4];
#pragma unroll
    for (int i = 0; i < 4; ++i) {
        float inv = g_invrs[b * LCc + c0 + ty * 4 + i];
        float2 a0 = unpack2(accA2[i][0]), a1 = unpack2(accA2[i][1]);
        float2 b0 = unpack2(accB2[i][0]), b1 = unpack2(accB2[i][1]);
        accA[i][0] = a0.x * inv; accA[i][1] = a0.y * inv;
        accA[i][2] = a1.x * inv; accA[i][3] = a1.y * inv;
        accB[i][0] = b0.x * inv; accB[i][1] = b0.y * inv;
        accB[i][2] = b1.x * inv; accB[i][3] = b1.y * inv;
    }
    // load C tile transposed: Cs[d][c] = C[c,b,d]
    {
        int cl = tid >> 2;
        int ds = (tid & 3) * 4;
#pragma unroll
        for (int dd = 0; dd < 64; dd += 16) {
            float4 cv = *(const float4*)(C + ((size_t)(c0 + cl) * NB + b) * ND + d0 + dd + ds);
            Cs[dd + ds + 0][cl] = cv.x; Cs[dd + ds + 1][cl] = cv.y;
            Cs[dd + ds + 2][cl] = cv.z; Cs[dd + ds + 3][cl] = cv.w;
        }
    }
#pragma unroll
    for (int i = 0; i < 4; ++i)
#pragma unroll
        for (int j = 0; j < 4; ++j) Tr[ty * 4 + i][tx * 4 + j] = accA[i][j];
    __syncthreads();
    const int cr = tid & 63;
    const int db = tid >> 6;
    const size_t ob = (size_t)b * (4 * ND) * LCc;
#pragma unroll
    for (int rr = 0; rr < 16; ++rr) {
        int dr = db + rr * 4;
        float cval = Cs[dr][cr];
        float aval = Tr[cr][dr];
        size_t col = (size_t)(c0 + cr);
        out[ob + (size_t)(d0 + dr) * LCc + col]            = cval;
        out[ob + (size_t)(ND + d0 + dr) * LCc + col]       = aval;
        out[ob + (size_t)(2 * ND + d0 + dr) * LCc + col]   = cval * aval;
    }
    __syncthreads();
#pragma unroll
    for (int i = 0; i < 4; ++i)
#pragma unroll
        for (int j = 0; j < 4; ++j) Tr[ty * 4 + i][tx * 4 + j] = accB[i][j];
    __syncthreads();
#pragma unroll
    for (int rr = 0; rr < 16; ++rr) {
        int dr = db + rr * 4;
        out[ob + (size_t)(3 * ND + d0 + dr) * LCc + (size_t)(c0 + cr)] = Cs[dr][cr] * Tr[cr][dr];
    }
}

// ---------------------------------------------------------------------------
extern "C" void kernel_launch(void* const* d_in, const int* in_sizes, int n_in,
                              void* d_out, int out_size) {
    const float* C     = (const float*)d_in[0];
    const float* Q     = (const float*)d_in[1];
    const float* w4C   = (const float*)d_in[2];
    const float* w4Q   = (const float*)d_in[3];
    const float* w4mlu = (const float*)d_in[4];
    const float* bias  = (const float*)d_in[5];
    float* out = (float*)d_out;

    k_init<<<(NB * LQq + 255) / 256, 256>>>();
    k0_sub<<<(NB * LCc + NB * LQq) / 8, 256>>>(C, Q, w4C, w4Q);
    k1_scores<<<dim3(LQq / 64, LCc / 64, NB), 256>>>(C, Q, w4mlu, bias);
    k2_row<<<NB * LCc / 8, 256>>>();
    k3_col<<<dim3(LQq / 128, LCc / 128, NB), 128>>>();
    k4_M<<<dim3(ND / 64, LQq / 64, NB), 256>>>(C);
    k5_out<<<dim3(ND / 64, LCc / 64, NB), 256>>>(C, Q, out);
}

// round 3
// speedup vs baseline: 1.2336x; 1.2023x over previous
#include <cuda_runtime.h>
#include <math.h>

#define LCc 1024
#define LQq 512
#define NB  64
#define ND  256

// ---------------- scratch ----------------------------------------------------
__device__ float g_E[(size_t)NB * LCc * LQq];   // E = exp(S)
__device__ float g_M[(size_t)NB * LQq * ND];    // M = E^T @ C / colsum
__device__ float g_sub0[NB * LCc];
__device__ float g_sub1[NB * LQq];
__device__ float g_invrs[NB * LCc];             // 1 / rowsum(E)
__device__ float g_csum2[NB * LQq];             // colsum(E)

// ---------------- packed f32x2 helpers ---------------------------------------
typedef unsigned long long u64t;
__device__ __forceinline__ u64t pack_dup(float a) {
    u64t r; asm("mov.b64 %0, {%1,%1};" : "=l"(r) : "f"(a)); return r;
}
__device__ __forceinline__ u64t pack2f(float lo, float hi) {
    u64t r; asm("mov.b64 %0, {%1,%2};" : "=l"(r) : "f"(lo), "f"(hi)); return r;
}
__device__ __forceinline__ void fma2(u64t& d, u64t a, u64t b) {
    asm("fma.rn.f32x2 %0, %1, %2, %0;" : "+l"(d) : "l"(a), "l"(b));
}
__device__ __forceinline__ float2 unpack2(u64t v) {
    float2 f; asm("mov.b64 {%0,%1}, %2;" : "=f"(f.x), "=f"(f.y) : "l"(v)); return f;
}

// ---------------- k_init ------------------------------------------------------
__global__ void k_init() {
    int i = blockIdx.x * blockDim.x + threadIdx.x;
    if (i < NB * LQq) g_csum2[i] = 0.f;
}

// ---------------- k0: sub0 = C@w4C, sub1 = Q@w4Q ------------------------------
__global__ __launch_bounds__(256) void k0_sub(const float* __restrict__ C,
                                              const float* __restrict__ Q,
                                              const float* __restrict__ w4C,
                                              const float* __restrict__ w4Q) {
    int gw   = (blockIdx.x * blockDim.x + threadIdx.x) >> 5;
    int lane = threadIdx.x & 31;
    const float* src; const float* w; float* dst;
    if (gw < NB * LCc) {
        src = C + (size_t)gw * ND;
        w   = w4C;
        int c = gw / NB, b = gw % NB;
        dst = g_sub0 + b * LCc + c;
    } else {
        int r = gw - NB * LCc;
        if (r >= NB * LQq) return;
        src = Q + (size_t)r * ND;
        w   = w4Q;
        int q = r / NB, b = r % NB;
        dst = g_sub1 + b * LQq + q;
    }
    float acc = 0.f;
    const float4* s4 = (const float4*)src;
    const float4* w4 = (const float4*)w;
#pragma unroll
    for (int j = 0; j < 2; ++j) {
        float4 a  = s4[lane + 32 * j];
        float4 ww = w4[lane + 32 * j];
        acc += a.x * ww.x + a.y * ww.y + a.z * ww.z + a.w * ww.w;
    }
#pragma unroll
    for (int off = 16; off; off >>= 1) acc += __shfl_xor_sync(0xffffffffu, acc, off);
    if (lane == 0) *dst = acc;
}

// ---------------- k1: E = exp(C @ (wml*Q)^T + sub0 + sub1 + bias) ------------
// 128x128 tile, 8x8 microtile, k-chunk 16
__global__ __launch_bounds__(256, 2) void k1_scores(const float* __restrict__ C,
                                                    const float* __restrict__ Q,
                                                    const float* __restrict__ w4mlu,
                                                    const float* __restrict__ bias) {
    __shared__ float As[16][132];
    __shared__ float Bs[16][132];
    __shared__ float wml[ND];
    const int b  = blockIdx.z;
    const int c0 = blockIdx.y * 128;
    const int q0 = blockIdx.x * 128;
    const int tid = threadIdx.x, tx = tid & 15, ty = tid >> 4;
    wml[tid] = w4mlu[tid];
    const int lrow = tid & 127, lk = (tid >> 7) * 8;
    const float* Ag = C + (size_t)(c0 + lrow) * (NB * ND) + (size_t)b * ND + lk;
    const float* Bg = Q + (size_t)(q0 + lrow) * (NB * ND) + (size_t)b * ND + lk;
    float4 pa0 = *(const float4*)(Ag);
    float4 pa1 = *(const float4*)(Ag + 4);
    float4 pb0 = *(const float4*)(Bg);
    float4 pb1 = *(const float4*)(Bg + 4);
    u64t acc[8][4] = {};
    __syncthreads();
    for (int k0 = 0; k0 < ND; k0 += 16) {
        As[lk + 0][lrow] = pa0.x; As[lk + 1][lrow] = pa0.y;
        As[lk + 2][lrow] = pa0.z; As[lk + 3][lrow] = pa0.w;
        As[lk + 4][lrow] = pa1.x; As[lk + 5][lrow] = pa1.y;
        As[lk + 6][lrow] = pa1.z; As[lk + 7][lrow] = pa1.w;
        Bs[lk + 0][lrow] = pb0.x * wml[k0 + lk + 0];
        Bs[lk + 1][lrow] = pb0.y * wml[k0 + lk + 1];
        Bs[lk + 2][lrow] = pb0.z * wml[k0 + lk + 2];
        Bs[lk + 3][lrow] = pb0.w * wml[k0 + lk + 3];
        Bs[lk + 4][lrow] = pb1.x * wml[k0 + lk + 4];
        Bs[lk + 5][lrow] = pb1.y * wml[k0 + lk + 5];
        Bs[lk + 6][lrow] = pb1.z * wml[k0 + lk + 6];
        Bs[lk + 7][lrow] = pb1.w * wml[k0 + lk + 7];
        __syncthreads();
        if (k0 + 16 < ND) {
            pa0 = *(const float4*)(Ag + k0 + 16);
            pa1 = *(const float4*)(Ag + k0 + 20);
            pb0 = *(const float4*)(Bg + k0 + 16);
            pb1 = *(const float4*)(Bg + k0 + 20);
        }
#pragma unroll
        for (int kk = 0; kk < 16; ++kk) {
            float4 a0 = *(const float4*)&As[kk][ty * 4];
            float4 a1 = *(const float4*)&As[kk][64 + ty * 4];
            float4 b0 = *(const float4*)&Bs[kk][tx * 4];
            float4 b1 = *(const float4*)&Bs[kk][64 + tx * 4];
            u64t bp0 = pack2f(b0.x, b0.y), bp1 = pack2f(b0.z, b0.w);
            u64t bp2 = pack2f(b1.x, b1.y), bp3 = pack2f(b1.z, b1.w);
            float ar[8] = {a0.x, a0.y, a0.z, a0.w, a1.x, a1.y, a1.z, a1.w};
#pragma unroll
            for (int i = 0; i < 8; ++i) {
                u64t ad = pack_dup(ar[i]);
                fma2(acc[i][0], ad, bp0);
                fma2(acc[i][1], ad, bp1);
                fma2(acc[i][2], ad, bp2);
                fma2(acc[i][3], ad, bp3);
            }
        }
        __syncthreads();
    }
    const float bv = bias[0];
    float s1v[8];
#pragma unroll
    for (int j = 0; j < 8; ++j) {
        int qj = q0 + ((j < 4) ? tx * 4 + j : 64 + tx * 4 + (j - 4));
        s1v[j] = g_sub1[b * LQq + qj];
    }
#pragma unroll
    for (int i = 0; i < 8; ++i) {
        int ri = c0 + ((i < 4) ? ty * 4 + i : 64 + ty * 4 + (i - 4));
        float s0 = g_sub0[b * LCc + ri] + bv;
        float2 p0 = unpack2(acc[i][0]), p1 = unpack2(acc[i][1]);
        float2 p2 = unpack2(acc[i][2]), p3 = unpack2(acc[i][3]);
        float4 o0, o1;
        o0.x = expf(p0.x + s0 + s1v[0]); o0.y = expf(p0.y + s0 + s1v[1]);
        o0.z = expf(p1.x + s0 + s1v[2]); o0.w = expf(p1.y + s0 + s1v[3]);
        o1.x = expf(p2.x + s0 + s1v[4]); o1.y = expf(p2.y + s0 + s1v[5]);
        o1.z = expf(p3.x + s0 + s1v[6]); o1.w = expf(p3.y + s0 + s1v[7]);
        float* dst = g_E + ((size_t)b * LCc + ri) * LQq + q0;
        *(float4*)(dst + tx * 4)      = o0;
        *(float4*)(dst + 64 + tx * 4) = o1;
    }
}

// ---------------- k23: rowsum (-> invrs) + colsum (-> csum2), one read pass ---
__global__ __launch_bounds__(256) void k23_sums() {
    const int b  = blockIdx.y;
    const int cb = blockIdx.x * 128;
    const int w = threadIdx.x >> 5, l = threadIdx.x & 31;
    float colacc[16] = {};
#pragma unroll 4
    for (int rr = 0; rr < 16; ++rr) {
        int c = cb + w + rr * 8;
        const float4* row = (const float4*)(g_E + ((size_t)b * LCc + c) * LQq);
        float rs = 0.f;
#pragma unroll
        for (int jj = 0; jj < 4; ++jj) {
            float4 v = row[l + 32 * jj];
            colacc[jj * 4 + 0] += v.x; colacc[jj * 4 + 1] += v.y;
            colacc[jj * 4 + 2] += v.z; colacc[jj * 4 + 3] += v.w;
            rs += v.x + v.y + v.z + v.w;
        }
#pragma unroll
        for (int off = 16; off; off >>= 1) rs += __shfl_xor_sync(0xffffffffu, rs, off);
        if (l == 0) g_invrs[b * LCc + c] = 1.0f / rs;
    }
#pragma unroll
    for (int jj = 0; jj < 4; ++jj)
#pragma unroll
        for (int t = 0; t < 4; ++t)
            atomicAdd(&g_csum2[b * LQq + 4 * l + 128 * jj + t], colacc[jj * 4 + t]);
}

// ---------------- k4: M = E^T @ C / colsum  (128x128 tile, 8x8 micro) ---------
__global__ __launch_bounds__(256, 2) void k4_M(const float* __restrict__ C) {
    __shared__ float As[16][132];
    __shared__ float Bs[16][132];
    const int b = blockIdx.z, q0 = blockIdx.y * 128, d0 = blockIdx.x * 128;
    const int tid = threadIdx.x, tx = tid & 15, ty = tid >> 4;
    const int lc4 = (tid & 31) * 4, lr = tid >> 5;
    const float* Ag = g_E + (size_t)b * LCc * LQq + q0 + lc4;
    const float* Bg = C + (size_t)b * ND + d0 + lc4;
    float4 pa0 = *(const float4*)(Ag + (size_t)lr * LQq);
    float4 pa1 = *(const float4*)(Ag + (size_t)(lr + 8) * LQq);
    float4 pb0 = *(const float4*)(Bg + (size_t)lr * (NB * ND));
    float4 pb1 = *(const float4*)(Bg + (size_t)(lr + 8) * (NB * ND));
    u64t acc[8][4] = {};
    for (int cb = 0; cb < LCc; cb += 16) {
        *(float4*)&As[lr][lc4]     = pa0;
        *(float4*)&As[lr + 8][lc4] = pa1;
        *(float4*)&Bs[lr][lc4]     = pb0;
        *(float4*)&Bs[lr + 8][lc4] = pb1;
        __syncthreads();
        if (cb + 16 < LCc) {
            pa0 = *(const float4*)(Ag + (size_t)(cb + 16 + lr) * LQq);
            pa1 = *(const float4*)(Ag + (size_t)(cb + 24 + lr) * LQq);
            pb0 = *(const float4*)(Bg + (size_t)(cb + 16 + lr) * (NB * ND));
            pb1 = *(const float4*)(Bg + (size_t)(cb + 24 + lr) * (NB * ND));
        }
#pragma unroll
        for (int kk = 0; kk < 16; ++kk) {
            float4 a0 = *(const float4*)&As[kk][ty * 4];
            float4 a1 = *(const float4*)&As[kk][64 + ty * 4];
            float4 b0 = *(const float4*)&Bs[kk][tx * 4];
            float4 b1 = *(const float4*)&Bs[kk][64 + tx * 4];
            u64t bp0 = pack2f(b0.x, b0.y), bp1 = pack2f(b0.z, b0.w);
            u64t bp2 = pack2f(b1.x, b1.y), bp3 = pack2f(b1.z, b1.w);
            float ar[8] = {a0.x, a0.y, a0.z, a0.w, a1.x, a1.y, a1.z, a1.w};
#pragma unroll
            for (int i = 0; i < 8; ++i) {
                u64t ad = pack_dup(ar[i]);
                fma2(acc[i][0], ad, bp0);
                fma2(acc[i][1], ad, bp1);
                fma2(acc[i][2], ad, bp2);
                fma2(acc[i][3], ad, bp3);
            }
        }
        __syncthreads();
    }
#pragma unroll
    for (int i = 0; i < 8; ++i) {
        int qi = q0 + ((i < 4) ? ty * 4 + i : 64 + ty * 4 + (i - 4));
        float inv = 1.0f / g_csum2[b * LQq + qi];
        float2 p0 = unpack2(acc[i][0]), p1 = unpack2(acc[i][1]);
        float2 p2 = unpack2(acc[i][2]), p3 = unpack2(acc[i][3]);
        float4 o0 = {p0.x * inv, p0.y * inv, p1.x * inv, p1.y * inv};
        float4 o1 = {p2.x * inv, p2.y * inv, p3.x * inv, p3.y * inv};
        float* dst = g_M + ((size_t)b * LQq + qi) * ND + d0;
        *(float4*)(dst + tx * 4)      = o0;
        *(float4*)(dst + 64 + tx * 4) = o1;
    }
}

// ---------------- k5: A = S1@Q, B_ = S1@M, fused transposed-concat ------------
// tile 128(c) x 64(d), dual 8x4 microtiles; smem reused between GEMM/epilogue
__global__ __launch_bounds__(256, 2) void k5_out(const float* __restrict__ C,
                                                 const float* __restrict__ Q,
                                                 float* __restrict__ out) {
    __shared__ __align__(16) float smem[8576];
    float (*As)[132] = (float(*)[132])smem;           // 16*132 = 2112 floats
    float (*Bq)[68]  = (float(*)[68])(smem + 2112);   // 16*68  = 1088
    float (*Bm)[68]  = (float(*)[68])(smem + 3200);   // 16*68  = 1088
    float (*Cs)[65]  = (float(*)[65])smem;            // 64*65  = 4160 (epilogue)
    float (*Tr)[69]  = (float(*)[69])(smem + 4160);   // 64*69  = 4416 (epilogue)
    const int b = blockIdx.z, c0 = blockIdx.y * 128, d0 = blockIdx.x * 64;
    const int tid = threadIdx.x, tx = tid & 15, ty = tid >> 4;
    const int lrow = tid & 127, lk = (tid >> 7) * 8;
    const float* Ag = g_E + ((size_t)b * LCc + c0 + lrow) * LQq + lk;
    const int qr = tid >> 4, bcol = (tid & 15) * 4;
    const float* Qg = Q + (size_t)b * ND + d0 + bcol;
    const float* Mg = g_M + (size_t)b * LQq * ND + d0 + bcol;
    float4 pa0 = *(const float4*)(Ag);
    float4 pa1 = *(const float4*)(Ag + 4);
    float4 pq  = *(const float4*)(Qg + (size_t)qr * (NB * ND));
    float4 pm  = *(const float4*)(Mg + (size_t)qr * ND);
    u64t accA[8][2] = {}, accB[8][2] = {};
    for (int k0 = 0; k0 < LQq; k0 += 16) {
        As[lk + 0][lrow] = pa0.x; As[lk + 1][lrow] = pa0.y;
        As[lk + 2][lrow] = pa0.z; As[lk + 3][lrow] = pa0.w;
        As[lk + 4][lrow] = pa1.x; As[lk + 5][lrow] = pa1.y;
        As[lk + 6][lrow] = pa1.z; As[lk + 7][lrow] = pa1.w;
        *(float4*)&Bq[qr][bcol] = pq;
        *(float4*)&Bm[qr][bcol] = pm;
        __syncthreads();
        if (k0 + 16 < LQq) {
            pa0 = *(const float4*)(Ag + k0 + 16);
            pa1 = *(const float4*)(Ag + k0 + 20);
            pq  = *(const float4*)(Qg + (size_t)(k0 + 16 + qr) * (NB * ND));
            pm  = *(const float4*)(Mg + (size_t)(k0 + 16 + qr) * ND);
        }
#pragma unroll
        for (int kk = 0; kk < 16; ++kk) {
            float4 a0 = *(const float4*)&As[kk][ty * 4];
            float4 a1 = *(const float4*)&As[kk][64 + ty * 4];
            float4 q4 = *(const float4*)&Bq[kk][tx * 4];
            float4 m4 = *(const float4*)&Bm[kk][tx * 4];
            u64t qp0 = pack2f(q4.x, q4.y), qp1 = pack2f(q4.z, q4.w);
            u64t mp0 = pack2f(m4.x, m4.y), mp1 = pack2f(m4.z, m4.w);
            float ar[8] = {a0.x, a0.y, a0.z, a0.w, a1.x, a1.y, a1.z, a1.w};
#pragma unroll
            for (int i = 0; i < 8; ++i) {
                u64t ad = pack_dup(ar[i]);
                fma2(accA[i][0], ad, qp0);
                fma2(accA[i][1], ad, qp1);
                fma2(accB[i][0], ad, mp0);
                fma2(accB[i][1], ad, mp1);
            }
        }
        __syncthreads();
    }
    float rA[8][4], rB[8][4];
#pragma unroll
    for (int i = 0; i < 8; ++i) {
        int ri = c0 + ((i < 4) ? ty * 4 + i : 64 + ty * 4 + (i - 4));
        float inv = g_invrs[b * LCc + ri];
        float2 a0 = unpack2(accA[i][0]), a1 = unpack2(accA[i][1]);
        float2 b0 = unpack2(accB[i][0]), b1 = unpack2(accB[i][1]);
        rA[i][0] = a0.x * inv; rA[i][1] = a0.y * inv;
        rA[i][2] = a1.x * inv; rA[i][3] = a1.y * inv;
        rB[i][0] = b0.x * inv; rB[i][1] = b0.y * inv;
        rB[i][2] = b1.x * inv; rB[i][3] = b1.y * inv;
    }
    const int cl = tid & 63, dseg = (tid >> 6) * 16;
    const int cr = tid & 63, db = tid >> 6;
    const size_t ob = (size_t)b * (4 * ND) * LCc;
    for (int h = 0; h < 2; ++h) {
        __syncthreads();   // GEMM smem / previous half fully consumed
        {   // load C tile for this half: Cs[d][c] = C[c0+h*64+cl, b, d0+d]
            const float* Cg = C + (size_t)(c0 + h * 64 + cl) * (NB * ND) + (size_t)b * ND + d0 + dseg;
#pragma unroll
            for (int dd = 0; dd < 16; dd += 4) {
                float4 cv = *(const float4*)(Cg + dd);
                Cs[dseg + dd + 0][cl] = cv.x; Cs[dseg + dd + 1][cl] = cv.y;
                Cs[dseg + dd + 2][cl] = cv.z; Cs[dseg + dd + 3][cl] = cv.w;
            }
        }
#pragma unroll
        for (int i = 0; i < 4; ++i)
#pragma unroll
            for (int j = 0; j < 4; ++j) Tr[ty * 4 + i][tx * 4 + j] = rA[h * 4 + i][j];
        __syncthreads();
#pragma unroll
        for (int rr = 0; rr < 16; ++rr) {
            int dr = db + rr * 4;
            float cval = Cs[dr][cr];
            float aval = Tr[cr][dr];
            size_t col = (size_t)(c0 + h * 64 + cr);
            out[ob + (size_t)(d0 + dr) * LCc + col]          = cval;
            out[ob + (size_t)(ND + d0 + dr) * LCc + col]     = aval;
            out[ob + (size_t)(2 * ND + d0 + dr) * LCc + col] = cval * aval;
        }
        __syncthreads();
#pragma unroll
        for (int i = 0; i < 4; ++i)
#pragma unroll
            for (int j = 0; j < 4; ++j) Tr[ty * 4 + i][tx * 4 + j] = rB[h * 4 + i][j];
        __syncthreads();
#pragma unroll
        for (int rr = 0; rr < 16; ++rr) {
            int dr = db + rr * 4;
            out[ob + (size_t)(3 * ND + d0 + dr) * LCc + (size_t)(c0 + h * 64 + cr)] =
                Cs[dr][cr] * Tr[cr][dr];
        }
    }
}

// ------------------------------------------------------------------------------
extern "C" void kernel_launch(void* const* d_in, const int* in_sizes, int n_in,
                              void* d_out, int out_size) {
    const float* C     = (const float*)d_in[0];
    const float* Q     = (const float*)d_in[1];
    const float* w4C   = (const float*)d_in[2];
    const float* w4Q   = (const float*)d_in[3];
    const float* w4mlu = (const float*)d_in[4];
    const float* bias  = (const float*)d_in[5];
    float* out = (float*)d_out;

    k_init<<<(NB * LQq + 255) / 256, 256>>>();
    k0_sub<<<(NB * LCc + NB * LQq) / 8, 256>>>(C, Q, w4C, w4Q);
    k1_scores<<<dim3(LQq / 128, LCc / 128, NB), 256>>>(C, Q, w4mlu, bias);
    k23_sums<<<dim3(LCc / 128, NB), 256>>>();
    k4_M<<<dim3(ND / 128, LQq / 128, NB), 256>>>(C);
    k5_out<<<dim3(ND / 64, LCc / 128, NB), 256>>>(C, Q, out);
}

// round 4
// speedup vs baseline: 1.6676x; 1.3518x over previous
#include <cuda_runtime.h>
#include <math.h>

#define LCc 1024
#define LQq 512
#define NB  64
#define ND  256

// ---------------- scratch ----------------------------------------------------
__device__ float g_E[(size_t)NB * LCc * LQq];   // E = exp(S)
__device__ float g_M[(size_t)NB * LQq * ND];    // M = E^T @ C / colsum
__device__ float g_sub0[NB * LCc];
__device__ float g_sub1[NB * LQq];
__device__ float g_invrs[NB * LCc];             // 1 / rowsum(E)
__device__ float g_csum2[NB * LQq];             // colsum(E)

// ---------------- tf32 helpers ------------------------------------------------
__device__ __forceinline__ float f2tf(float f) {
    unsigned r; asm("cvt.rna.tf32.f32 %0, %1;" : "=r"(r) : "f"(f));
    return __uint_as_float(r);
}
__device__ __forceinline__ void mma8(float4& d,
        unsigned a0, unsigned a1, unsigned a2, unsigned a3,
        unsigned b0, unsigned b1) {
    asm volatile("mma.sync.aligned.m16n8k8.row.col.f32.tf32.tf32.f32 "
        "{%0,%1,%2,%3}, {%4,%5,%6,%7}, {%8,%9}, {%0,%1,%2,%3};"
        : "+f"(d.x), "+f"(d.y), "+f"(d.z), "+f"(d.w)
        : "r"(a0), "r"(a1), "r"(a2), "r"(a3), "r"(b0), "r"(b1));
}
__device__ __forceinline__ unsigned ldu(const float* p) {
    return __float_as_uint(*p);
}

// ---------------- k_init ------------------------------------------------------
__global__ void k_init() {
    int i = blockIdx.x * blockDim.x + threadIdx.x;
    if (i < NB * LQq) g_csum2[i] = 0.f;
}

// ---------------- k0: sub0 = C@w4C, sub1 = Q@w4Q ------------------------------
__global__ __launch_bounds__(256) void k0_sub(const float* __restrict__ C,
                                              const float* __restrict__ Q,
                                              const float* __restrict__ w4C,
                                              const float* __restrict__ w4Q) {
    int gw   = (blockIdx.x * blockDim.x + threadIdx.x) >> 5;
    int lane = threadIdx.x & 31;
    const float* src; const float* w; float* dst;
    if (gw < NB * LCc) {
        src = C + (size_t)gw * ND;
        w   = w4C;
        int c = gw / NB, b = gw % NB;
        dst = g_sub0 + b * LCc + c;
    } else {
        int r = gw - NB * LCc;
        if (r >= NB * LQq) return;
        src = Q + (size_t)r * ND;
        w   = w4Q;
        int q = r / NB, b = r % NB;
        dst = g_sub1 + b * LQq + q;
    }
    float acc = 0.f;
    const float4* s4 = (const float4*)src;
    const float4* w4 = (const float4*)w;
#pragma unroll
    for (int j = 0; j < 2; ++j) {
        float4 a  = s4[lane + 32 * j];
        float4 ww = w4[lane + 32 * j];
        acc += a.x * ww.x + a.y * ww.y + a.z * ww.z + a.w * ww.w;
    }
#pragma unroll
    for (int off = 16; off; off >>= 1) acc += __shfl_xor_sync(0xffffffffu, acc, off);
    if (lane == 0) *dst = acc;
}

// ---------------- k1: E = exp(C @ (wml*Q)^T + sub0 + sub1 + bias) -------------
// tensor-core tf32; CTA 128(c) x 128(q), warp 64x32, k-chunk 16 over d
__global__ __launch_bounds__(256) void k1_scores(const float* __restrict__ C,
                                                 const float* __restrict__ Q,
                                                 const float* __restrict__ w4mlu,
                                                 const float* __restrict__ bias) {
    __shared__ float As[16][132];   // [k=d][m=c]  tf32 bits
    __shared__ float Bs[16][132];   // [k=d][n=q]  tf32 bits (pre-multiplied by wml)
    __shared__ float wml[ND];
    const int b = blockIdx.z, c0 = blockIdx.y * 128, q0 = blockIdx.x * 128;
    const int tid = threadIdx.x;
    wml[tid] = w4mlu[tid];
    const int lane = tid & 31, w = tid >> 5;
    const int g = lane >> 2, t = lane & 3;
    const int mbase = (w >> 2) * 64, nbase = (w & 3) * 32;
    const int lrow = tid & 127, lks = (tid >> 7) * 8;
    const float* Ag = C + (size_t)(c0 + lrow) * (NB * ND) + (size_t)b * ND + lks;
    const float* Bg = Q + (size_t)(q0 + lrow) * (NB * ND) + (size_t)b * ND + lks;
    float4 pa0 = *(const float4*)Ag;
    float4 pa1 = *(const float4*)(Ag + 4);
    float4 pb0 = *(const float4*)Bg;
    float4 pb1 = *(const float4*)(Bg + 4);
    float4 acc[4][4] = {};
    __syncthreads();
    for (int k0 = 0; k0 < ND; k0 += 16) {
        As[lks + 0][lrow] = f2tf(pa0.x); As[lks + 1][lrow] = f2tf(pa0.y);
        As[lks + 2][lrow] = f2tf(pa0.z); As[lks + 3][lrow] = f2tf(pa0.w);
        As[lks + 4][lrow] = f2tf(pa1.x); As[lks + 5][lrow] = f2tf(pa1.y);
        As[lks + 6][lrow] = f2tf(pa1.z); As[lks + 7][lrow] = f2tf(pa1.w);
        Bs[lks + 0][lrow] = f2tf(pb0.x * wml[k0 + lks + 0]);
        Bs[lks + 1][lrow] = f2tf(pb0.y * wml[k0 + lks + 1]);
        Bs[lks + 2][lrow] = f2tf(pb0.z * wml[k0 + lks + 2]);
        Bs[lks + 3][lrow] = f2tf(pb0.w * wml[k0 + lks + 3]);
        Bs[lks + 4][lrow] = f2tf(pb1.x * wml[k0 + lks + 4]);
        Bs[lks + 5][lrow] = f2tf(pb1.y * wml[k0 + lks + 5]);
        Bs[lks + 6][lrow] = f2tf(pb1.z * wml[k0 + lks + 6]);
        Bs[lks + 7][lrow] = f2tf(pb1.w * wml[k0 + lks + 7]);
        __syncthreads();
        if (k0 + 16 < ND) {
            pa0 = *(const float4*)(Ag + k0 + 16);
            pa1 = *(const float4*)(Ag + k0 + 20);
            pb0 = *(const float4*)(Bg + k0 + 16);
            pb1 = *(const float4*)(Bg + k0 + 20);
        }
#pragma unroll
        for (int kk = 0; kk < 16; kk += 8) {
            unsigned af[4][4], bf[4][2];
#pragma unroll
            for (int mi = 0; mi < 4; ++mi) {
                int m = mbase + mi * 16 + g;
                af[mi][0] = ldu(&As[kk + t][m]);
                af[mi][1] = ldu(&As[kk + t][m + 8]);
                af[mi][2] = ldu(&As[kk + t + 4][m]);
                af[mi][3] = ldu(&As[kk + t + 4][m + 8]);
            }
#pragma unroll
            for (int ni = 0; ni < 4; ++ni) {
                int n = nbase + ni * 8 + g;
                bf[ni][0] = ldu(&Bs[kk + t][n]);
                bf[ni][1] = ldu(&Bs[kk + t + 4][n]);
            }
#pragma unroll
            for (int mi = 0; mi < 4; ++mi)
#pragma unroll
                for (int ni = 0; ni < 4; ++ni)
                    mma8(acc[mi][ni], af[mi][0], af[mi][1], af[mi][2], af[mi][3],
                         bf[ni][0], bf[ni][1]);
        }
        __syncthreads();
    }
    const float bv = bias[0];
    float s1x[4], s1y[4];
#pragma unroll
    for (int ni = 0; ni < 4; ++ni) {
        int q = q0 + nbase + ni * 8 + 2 * t;
        s1x[ni] = g_sub1[b * LQq + q];
        s1y[ni] = g_sub1[b * LQq + q + 1];
    }
#pragma unroll
    for (int mi = 0; mi < 4; ++mi) {
        int cA = c0 + mbase + mi * 16 + g;
        float s0a = g_sub0[b * LCc + cA] + bv;
        float s0b = g_sub0[b * LCc + cA + 8] + bv;
        float* r0 = g_E + ((size_t)b * LCc + cA) * LQq + q0;
        float* r1 = r0 + 8 * LQq;
#pragma unroll
        for (int ni = 0; ni < 4; ++ni) {
            int q = nbase + ni * 8 + 2 * t;
            float2 e0 = {expf(acc[mi][ni].x + s0a + s1x[ni]),
                         expf(acc[mi][ni].y + s0a + s1y[ni])};
            float2 e1 = {expf(acc[mi][ni].z + s0b + s1x[ni]),
                         expf(acc[mi][ni].w + s0b + s1y[ni])};
            *(float2*)(r0 + q) = e0;
            *(float2*)(r1 + q) = e1;
        }
    }
}

// ---------------- k23: rowsum (-> invrs) + colsum (-> csum2) -----------------
__global__ __launch_bounds__(256) void k23_sums() {
    const int b  = blockIdx.y;
    const int cb = blockIdx.x * 128;
    const int w = threadIdx.x >> 5, l = threadIdx.x & 31;
    float colacc[16] = {};
#pragma unroll 4
    for (int rr = 0; rr < 16; ++rr) {
        int c = cb + w + rr * 8;
        const float4* row = (const float4*)(g_E + ((size_t)b * LCc + c) * LQq);
        float rs = 0.f;
#pragma unroll
        for (int jj = 0; jj < 4; ++jj) {
            float4 v = row[l + 32 * jj];
            colacc[jj * 4 + 0] += v.x; colacc[jj * 4 + 1] += v.y;
            colacc[jj * 4 + 2] += v.z; colacc[jj * 4 + 3] += v.w;
            rs += v.x + v.y + v.z + v.w;
        }
#pragma unroll
        for (int off = 16; off; off >>= 1) rs += __shfl_xor_sync(0xffffffffu, rs, off);
        if (l == 0) g_invrs[b * LCc + c] = 1.0f / rs;
    }
#pragma unroll
    for (int jj = 0; jj < 4; ++jj)
#pragma unroll
        for (int tt = 0; tt < 4; ++tt)
            atomicAdd(&g_csum2[b * LQq + 4 * l + 128 * jj + tt], colacc[jj * 4 + tt]);
}

// ---------------- k4: M = E^T @ C / colsum ------------------------------------
// CTA 128(q) x 128(d), warp 64x32, k-chunk 16 over c (no transpose staging)
__global__ __launch_bounds__(256) void k4_M(const float* __restrict__ C) {
    __shared__ float As[16][132];   // [k=c][m=q]
    __shared__ float Bs[16][132];   // [k=c][n=d]
    const int b = blockIdx.z, q0 = blockIdx.y * 128, d0 = blockIdx.x * 128;
    const int tid = threadIdx.x;
    const int lane = tid & 31, w = tid >> 5;
    const int g = lane >> 2, t = lane & 3;
    const int mbase = (w >> 2) * 64, nbase = (w & 3) * 32;
    const int l4 = (lane) * 4 % 128;        // (tid & 31) * 4
    const int crr = tid >> 5;               // 0..7
    const float* Ag = g_E + ((size_t)b * LCc + crr) * LQq + q0 + l4;
    const float* Bg = C + (size_t)crr * (NB * ND) + (size_t)b * ND + d0 + l4;
    float4 pa0 = *(const float4*)Ag;
    float4 pa1 = *(const float4*)(Ag + (size_t)8 * LQq);
    float4 pb0 = *(const float4*)Bg;
    float4 pb1 = *(const float4*)(Bg + (size_t)8 * (NB * ND));
    float4 acc[4][4] = {};
    for (int cb = 0; cb < LCc; cb += 16) {
        float4 ta = {f2tf(pa0.x), f2tf(pa0.y), f2tf(pa0.z), f2tf(pa0.w)};
        *(float4*)&As[crr][l4] = ta;
        ta = make_float4(f2tf(pa1.x), f2tf(pa1.y), f2tf(pa1.z), f2tf(pa1.w));
        *(float4*)&As[crr + 8][l4] = ta;
        ta = make_float4(f2tf(pb0.x), f2tf(pb0.y), f2tf(pb0.z), f2tf(pb0.w));
        *(float4*)&Bs[crr][l4] = ta;
        ta = make_float4(f2tf(pb1.x), f2tf(pb1.y), f2tf(pb1.z), f2tf(pb1.w));
        *(float4*)&Bs[crr + 8][l4] = ta;
        __syncthreads();
        if (cb + 16 < LCc) {
            pa0 = *(const float4*)(Ag + (size_t)(cb + 16) * LQq);
            pa1 = *(const float4*)(Ag + (size_t)(cb + 24) * LQq);
            pb0 = *(const float4*)(Bg + (size_t)(cb + 16) * (NB * ND));
            pb1 = *(const float4*)(Bg + (size_t)(cb + 24) * (NB * ND));
        }
#pragma unroll
        for (int kk = 0; kk < 16; kk += 8) {
            unsigned af[4][4], bf[4][2];
#pragma unroll
            for (int mi = 0; mi < 4; ++mi) {
                int m = mbase + mi * 16 + g;
                af[mi][0] = ldu(&As[kk + t][m]);
                af[mi][1] = ldu(&As[kk + t][m + 8]);
                af[mi][2] = ldu(&As[kk + t + 4][m]);
                af[mi][3] = ldu(&As[kk + t + 4][m + 8]);
            }
#pragma unroll
            for (int ni = 0; ni < 4; ++ni) {
                int n = nbase + ni * 8 + g;
                bf[ni][0] = ldu(&Bs[kk + t][n]);
                bf[ni][1] = ldu(&Bs[kk + t + 4][n]);
            }
#pragma unroll
            for (int mi = 0; mi < 4; ++mi)
#pragma unroll
                for (int ni = 0; ni < 4; ++ni)
                    mma8(acc[mi][ni], af[mi][0], af[mi][1], af[mi][2], af[mi][3],
                         bf[ni][0], bf[ni][1]);
        }
        __syncthreads();
    }
#pragma unroll
    for (int mi = 0; mi < 4; ++mi) {
        int qA = q0 + mbase + mi * 16 + g;
        float i0 = 1.0f / g_csum2[b * LQq + qA];
        float i1 = 1.0f / g_csum2[b * LQq + qA + 8];
        float* r0 = g_M + ((size_t)b * LQq + qA) * ND + d0;
        float* r1 = r0 + 8 * ND;
#pragma unroll
        for (int ni = 0; ni < 4; ++ni) {
            int d = nbase + ni * 8 + 2 * t;
            float2 o0 = {acc[mi][ni].x * i0, acc[mi][ni].y * i0};
            float2 o1 = {acc[mi][ni].z * i1, acc[mi][ni].w * i1};
            *(float2*)(r0 + d) = o0;
            *(float2*)(r1 + d) = o1;
        }
    }
}

// ---------------- k5: A = S1@Q, B_ = S1@M, fused transposed-concat ------------
// CTA 128(c) x 64(d), warp 32x32 dual-output, k-chunk 16 over q
__global__ __launch_bounds__(256) void k5_out(const float* __restrict__ C,
                                              const float* __restrict__ Q,
                                              float* __restrict__ out) {
    __shared__ __align__(16) float smem[8576];
    float (*As)[132] = (float(*)[132])smem;           // [k=q 16][c 128]
    float (*Bq)[68]  = (float(*)[68])(smem + 2112);   // [k=q 16][d 64]
    float (*Bm)[68]  = (float(*)[68])(smem + 3200);
    float (*Cs)[65]  = (float(*)[65])smem;            // epilogue: [d][c]
    float (*Tr)[69]  = (float(*)[69])(smem + 4160);   // epilogue: [c][d]
    const int b = blockIdx.z, c0 = blockIdx.y * 128, d0 = blockIdx.x * 64;
    const int tid = threadIdx.x;
    const int lane = tid & 31, w = tid >> 5;
    const int g = lane >> 2, t = lane & 3;
    const int wr = w >> 1, wc = w & 1;
    const int mbase = wr * 32, nbase = wc * 32;
    const int lrow = tid & 127, lks = (tid >> 7) * 8;
    const int qr = tid >> 4, dl = (tid & 15) * 4;
    const float* Ag = g_E + ((size_t)b * LCc + c0 + lrow) * LQq + lks;
    const float* Qg = Q + (size_t)b * ND + d0 + dl;
    const float* Mg = g_M + (size_t)b * LQq * ND + d0 + dl;
    float4 pa0 = *(const float4*)Ag;
    float4 pa1 = *(const float4*)(Ag + 4);
    float4 pq  = *(const float4*)(Qg + (size_t)qr * (NB * ND));
    float4 pm  = *(const float4*)(Mg + (size_t)qr * ND);
    float4 accA[2][4] = {}, accB[2][4] = {};
    for (int k0 = 0; k0 < LQq; k0 += 16) {
        As[lks + 0][lrow] = f2tf(pa0.x); As[lks + 1][lrow] = f2tf(pa0.y);
        As[lks + 2][lrow] = f2tf(pa0.z); As[lks + 3][lrow] = f2tf(pa0.w);
        As[lks + 4][lrow] = f2tf(pa1.x); As[lks + 5][lrow] = f2tf(pa1.y);
        As[lks + 6][lrow] = f2tf(pa1.z); As[lks + 7][lrow] = f2tf(pa1.w);
        float4 tq = {f2tf(pq.x), f2tf(pq.y), f2tf(pq.z), f2tf(pq.w)};
        *(float4*)&Bq[qr][dl] = tq;
        float4 tm = {f2tf(pm.x), f2tf(pm.y), f2tf(pm.z), f2tf(pm.w)};
        *(float4*)&Bm[qr][dl] = tm;
        __syncthreads();
        if (k0 + 16 < LQq) {
            pa0 = *(const float4*)(Ag + k0 + 16);
            pa1 = *(const float4*)(Ag + k0 + 20);
            pq  = *(const float4*)(Qg + (size_t)(k0 + 16 + qr) * (NB * ND));
            pm  = *(const float4*)(Mg + (size_t)(k0 + 16 + qr) * ND);
        }
#pragma unroll
        for (int kk = 0; kk < 16; kk += 8) {
            unsigned af[2][4], qf[4][2], mf[4][2];
#pragma unroll
            for (int mi = 0; mi < 2; ++mi) {
                int m = mbase + mi * 16 + g;
                af[mi][0] = ldu(&As[kk + t][m]);
                af[mi][1] = ldu(&As[kk + t][m + 8]);
                af[mi][2] = ldu(&As[kk + t + 4][m]);
                af[mi][3] = ldu(&As[kk + t + 4][m + 8]);
            }
#pragma unroll
            for (int ni = 0; ni < 4; ++ni) {
                int n = nbase + ni * 8 + g;
                qf[ni][0] = ldu(&Bq[kk + t][n]);
                qf[ni][1] = ldu(&Bq[kk + t + 4][n]);
                mf[ni][0] = ldu(&Bm[kk + t][n]);
                mf[ni][1] = ldu(&Bm[kk + t + 4][n]);
            }
#pragma unroll
            for (int mi = 0; mi < 2; ++mi)
#pragma unroll
                for (int ni = 0; ni < 4; ++ni) {
                    mma8(accA[mi][ni], af[mi][0], af[mi][1], af[mi][2], af[mi][3],
                         qf[ni][0], qf[ni][1]);
                    mma8(accB[mi][ni], af[mi][0], af[mi][1], af[mi][2], af[mi][3],
                         mf[ni][0], mf[ni][1]);
                }
        }
        __syncthreads();
    }
#pragma unroll
    for (int mi = 0; mi < 2; ++mi) {
        int cA = c0 + mbase + mi * 16 + g;
        float i0 = g_invrs[b * LCc + cA];
        float i1 = g_invrs[b * LCc + cA + 8];
#pragma unroll
        for (int ni = 0; ni < 4; ++ni) {
            accA[mi][ni].x *= i0; accA[mi][ni].y *= i0;
            accA[mi][ni].z *= i1; accA[mi][ni].w *= i1;
            accB[mi][ni].x *= i0; accB[mi][ni].y *= i0;
            accB[mi][ni].z *= i1; accB[mi][ni].w *= i1;
        }
    }
    const int cl = tid & 63, dseg = (tid >> 6) * 16;
    const int cr = tid & 63, db = tid >> 6;
    const size_t ob = (size_t)b * (4 * ND) * LCc;
    for (int h = 0; h < 2; ++h) {
        __syncthreads();
        {   // load C tile: Cs[d][c] = C[c0+h*64+cl, b, d0+d]
            const float* Cg = C + (size_t)(c0 + h * 64 + cl) * (NB * ND) + (size_t)b * ND + d0 + dseg;
#pragma unroll
            for (int dd = 0; dd < 16; dd += 4) {
                float4 cv = *(const float4*)(Cg + dd);
                Cs[dseg + dd + 0][cl] = cv.x; Cs[dseg + dd + 1][cl] = cv.y;
                Cs[dseg + dd + 2][cl] = cv.z; Cs[dseg + dd + 3][cl] = cv.w;
            }
        }
        if ((w >> 2) == h) {
#pragma unroll
            for (int mi = 0; mi < 2; ++mi) {
                int clh = (wr & 1) * 32 + mi * 16 + g;
#pragma unroll
                for (int ni = 0; ni < 4; ++ni) {
                    int d = nbase + ni * 8 + 2 * t;
                    Tr[clh][d]     = accA[mi][ni].x;
                    Tr[clh][d + 1] = accA[mi][ni].y;
                    Tr[clh + 8][d]     = accA[mi][ni].z;
                    Tr[clh + 8][d + 1] = accA[mi][ni].w;
                }
            }
        }
        __syncthreads();
#pragma unroll
        for (int rr = 0; rr < 16; ++rr) {
            int dr = db + rr * 4;
            float cval = Cs[dr][cr];
            float aval = Tr[cr][dr];
            size_t col = (size_t)(c0 + h * 64 + cr);
            out[ob + (size_t)(d0 + dr) * LCc + col]          = cval;
            out[ob + (size_t)(ND + d0 + dr) * LCc + col]     = aval;
            out[ob + (size_t)(2 * ND + d0 + dr) * LCc + col] = cval * aval;
        }
        __syncthreads();
        if ((w >> 2) == h) {
#pragma unroll
            for (int mi = 0; mi < 2; ++mi) {
                int clh = (wr & 1) * 32 + mi * 16 + g;
#pragma unroll
                for (int ni = 0; ni < 4; ++ni) {
                    int d = nbase + ni * 8 + 2 * t;
                    Tr[clh][d]     = accB[mi][ni].x;
                    Tr[clh][d + 1] = accB[mi][ni].y;
                    Tr[clh + 8][d]     = accB[mi][ni].z;
                    Tr[clh + 8][d + 1] = accB[mi][ni].w;
                }
            }
        }
        __syncthreads();
#pragma unroll
        for (int rr = 0; rr < 16; ++rr) {
            int dr = db + rr * 4;
            out[ob + (size_t)(3 * ND + d0 + dr) * LCc + (size_t)(c0 + h * 64 + cr)] =
                Cs[dr][cr] * Tr[cr][dr];
        }
    }
}

// ------------------------------------------------------------------------------
extern "C" void kernel_launch(void* const* d_in, const int* in_sizes, int n_in,
                              void* d_out, int out_size) {
    const float* C     = (const float*)d_in[0];
    const float* Q     = (const float*)d_in[1];
    const float* w4C   = (const float*)d_in[2];
    const float* w4Q   = (const float*)d_in[3];
    const float* w4mlu = (const float*)d_in[4];
    const float* bias  = (const float*)d_in[5];
    float* out = (float*)d_out;

    k_init<<<(NB * LQq + 255) / 256, 256>>>();
    k0_sub<<<(NB * LCc + NB * LQq) / 8, 256>>>(C, Q, w4C, w4Q);
    k1_scores<<<dim3(LQq / 128, LCc / 128, NB), 256>>>(C, Q, w4mlu, bias);
    k23_sums<<<dim3(LCc / 128, NB), 256>>>();
    k4_M<<<dim3(ND / 128, LQq / 128, NB), 256>>>(C);
    k5_out<<<dim3(ND / 64, LCc / 128, NB), 256>>>(C, Q, out);
}